// round 1
// baseline (speedup 1.0000x reference)
#include <cuda_runtime.h>
#include <math.h>

// Problem constants (fixed by the reference):
//   B=2048, T=64, IN=8, HID=6 (qubits), OUT=8, NLAYERS=2, concat=16
#define NB    2048
#define NT    64
#define NIN   8
#define NHID  6
#define NOUT  8
#define NCAT  16
#define NLAY  2

__device__ __forceinline__ float sigmoidf_(float v) {
    return 1.0f / (1.0f + __expf(-v));
}
__device__ __forceinline__ float tanhfast_(float v) {
    return 2.0f / (1.0f + __expf(-2.0f * v)) - 1.0f;
}

// One warp simulates one batch element end-to-end (all 64 timesteps).
// 6-qubit state = 64 complex amps; amp index = lane*2 + slot.
//   wire w (0..4)  <-> lane bit (4-w)   -> shuffle-xor mixing
//   wire 5         <-> slot bit          -> in-thread mixing
__global__ __launch_bounds__(128) void qlstm_kernel(
    const float* __restrict__ x,      // [B, T, IN]
    const float* __restrict__ W_in,   // [HID, 16]
    const float* __restrict__ b_in,   // [HID]
    const float* __restrict__ W_out,  // [OUT, HID]
    const float* __restrict__ b_out,  // [OUT]
    const float* __restrict__ wf,     // [NLAY, HID]
    const float* __restrict__ wi,
    const float* __restrict__ wg,
    const float* __restrict__ wo,
    float* __restrict__ out)          // [B, T, OUT]
{
    __shared__ float sWin[NHID][NCAT];
    __shared__ float sbin[NHID];
    __shared__ float sWout[NOUT][NHID];
    __shared__ float sbout[NOUT];
    __shared__ float sC[4][NLAY][NHID];   // cos(0.5*theta) of layer weights
    __shared__ float sS[4][NLAY][NHID];   // sin(0.5*theta)

    const int tid = threadIdx.x;

    if (tid < NHID * NCAT) sWin[tid / NCAT][tid % NCAT] = W_in[tid];
    if (tid < NHID)        sbin[tid] = b_in[tid];
    if (tid < NOUT * NHID) sWout[tid / NHID][tid % NHID] = W_out[tid];
    if (tid < NOUT)        sbout[tid] = b_out[tid];
    if (tid < 4 * NLAY * NHID) {
        const float* wp[4] = {wf, wi, wg, wo};
        int g = tid / (NLAY * NHID);
        int r = tid % (NLAY * NHID);
        float th = wp[g][r];
        float s_, c_;
        sincosf(0.5f * th, &s_, &c_);
        sC[g][r / NHID][r % NHID] = c_;
        sS[g][r / NHID][r % NHID] = s_;
    }
    __syncthreads();

    const int warp = blockIdx.x * (blockDim.x >> 5) + (tid >> 5);
    const int lane = tid & 31;
    const unsigned FULL = 0xffffffffu;
    if (warp >= NB) return;

    // LSTM state: lane j (<8) holds h_j, c_j.
    float h = 0.0f, c = 0.0f;

    // Hoist per-lane W_out row (lane & 7 -> output dim j).
    const int jl = lane & 7;
    float wrow[NHID];
    #pragma unroll
    for (int w = 0; w < NHID; w++) wrow[w] = sWout[jl][w];
    const float bj = sbout[jl];

    // Precompute reduction sign masks for this lane (wires 0..4 -> lane bits 4..0)
    float sgn[5];
    #pragma unroll
    for (int w = 0; w < 5; w++) sgn[w] = ((lane >> (4 - w)) & 1) ? -1.0f : 1.0f;

    const float* xrow = x + (size_t)warp * NT * NIN;
    float* orow = out + (size_t)warp * NT * NOUT;

    #pragma unroll 1
    for (int t = 0; t < NT; t++) {
        // ---- y = [h, x_t] @ W_in^T + b_in : lanes 0..5 compute y_k ----
        float v = 0.0f;
        if (lane < 8)        v = h;
        else if (lane < 16)  v = xrow[t * NIN + (lane - 8)];

        float y = 0.0f;
        if (lane < NHID) y = sbin[lane];
        #pragma unroll
        for (int j = 0; j < NCAT; j++) {
            float vj = __shfl_sync(FULL, v, j);
            if (lane < NHID) y = fmaf(sWin[lane][j], vj, y);
        }
        // sincos on lanes 0..5, broadcast cos/sin of each wire to all lanes
        float myS, myC;
        __sincosf(0.5f * y, &myS, &myC);
        float cw[NHID], sw[NHID];
        #pragma unroll
        for (int w = 0; w < NHID; w++) {
            cw[w] = __shfl_sync(FULL, myC, w);
            sw[w] = __shfl_sync(FULL, myS, w);
        }

        // ---- embedding RX on |0...0> (shared by all 4 gate circuits) ----
        float r0 = (lane == 0) ? 1.0f : 0.0f, i0 = 0.0f;
        float r1 = 0.0f, i1 = 0.0f;
        #pragma unroll
        for (int w = 0; w < 5; w++) {
            const int m = 1 << (4 - w);
            float pr0 = __shfl_xor_sync(FULL, r0, m);
            float pi0 = __shfl_xor_sync(FULL, i0, m);
            float pr1 = __shfl_xor_sync(FULL, r1, m);
            float pi1 = __shfl_xor_sync(FULL, i1, m);
            float cc = cw[w], ss = sw[w];
            r0 = fmaf(cc, r0, ss * pi0);
            i0 = fmaf(cc, i0, -ss * pr0);
            r1 = fmaf(cc, r1, ss * pi1);
            i1 = fmaf(cc, i1, -ss * pr1);
        }
        {   // wire 5 (in-thread)
            float cc = cw[5], ss = sw[5];
            float nr0 = fmaf(cc, r0, ss * i1);
            float ni0 = fmaf(cc, i0, -ss * r1);
            float nr1 = fmaf(cc, r1, ss * i0);
            float ni1 = fmaf(cc, i1, -ss * r0);
            r0 = nr0; i0 = ni0; r1 = nr1; i1 = ni1;
        }

        // ---- replicate to 4 gate circuits (f, i, g, o) ----
        float gr0[4], gi0[4], gr1[4], gi1[4];
        #pragma unroll
        for (int g = 0; g < 4; g++) { gr0[g] = r0; gi0[g] = i0; gr1[g] = r1; gi1[g] = i1; }

        // ---- entangler layers: RX(weights) + CNOT ring, interleaved over gates ----
        #pragma unroll
        for (int l = 0; l < NLAY; l++) {
            #pragma unroll
            for (int w = 0; w < 5; w++) {
                const int m = 1 << (4 - w);
                #pragma unroll
                for (int g = 0; g < 4; g++) {
                    float pr0 = __shfl_xor_sync(FULL, gr0[g], m);
                    float pi0 = __shfl_xor_sync(FULL, gi0[g], m);
                    float pr1 = __shfl_xor_sync(FULL, gr1[g], m);
                    float pi1 = __shfl_xor_sync(FULL, gi1[g], m);
                    float cc = sC[g][l][w], ss = sS[g][l][w];
                    gr0[g] = fmaf(cc, gr0[g], ss * pi0);
                    gi0[g] = fmaf(cc, gi0[g], -ss * pr0);
                    gr1[g] = fmaf(cc, gr1[g], ss * pi1);
                    gi1[g] = fmaf(cc, gi1[g], -ss * pr1);
                }
            }
            #pragma unroll
            for (int g = 0; g < 4; g++) {   // wire-5 RX (in-thread)
                float cc = sC[g][l][5], ss = sS[g][l][5];
                float nr0 = fmaf(cc, gr0[g], ss * gi1[g]);
                float ni0 = fmaf(cc, gi0[g], -ss * gr1[g]);
                float nr1 = fmaf(cc, gr1[g], ss * gi0[g]);
                float ni1 = fmaf(cc, gi1[g], -ss * gr0[g]);
                gr0[g] = nr0; gi0[g] = ni0; gr1[g] = nr1; gi1[g] = ni1;
            }
            // CNOT (cwr, cwr+1) for cwr = 0..3: ctrl & tgt both lane bits
            #pragma unroll
            for (int cwr = 0; cwr < 4; cwr++) {
                const int m = 1 << (3 - cwr);              // tgt wire cwr+1
                const bool ctrl = (lane >> (4 - cwr)) & 1; // ctrl wire cwr
                #pragma unroll
                for (int g = 0; g < 4; g++) {
                    float t0 = __shfl_xor_sync(FULL, gr0[g], m);
                    float t1 = __shfl_xor_sync(FULL, gi0[g], m);
                    float t2 = __shfl_xor_sync(FULL, gr1[g], m);
                    float t3 = __shfl_xor_sync(FULL, gi1[g], m);
                    if (ctrl) { gr0[g] = t0; gi0[g] = t1; gr1[g] = t2; gi1[g] = t3; }
                }
            }
            // CNOT (4,5): ctrl = lane bit0, tgt = slot -> in-thread swap
            {
                const bool c45 = lane & 1;
                #pragma unroll
                for (int g = 0; g < 4; g++) {
                    float a0 = gr0[g], b0 = gi0[g];
                    gr0[g] = c45 ? gr1[g] : gr0[g];
                    gi0[g] = c45 ? gi1[g] : gi0[g];
                    gr1[g] = c45 ? a0 : gr1[g];
                    gi1[g] = c45 ? b0 : gi1[g];
                }
            }
            // CNOT (5,0): ctrl = slot bit -> slot-1 amps exchange with lane^16
            #pragma unroll
            for (int g = 0; g < 4; g++) {
                gr1[g] = __shfl_xor_sync(FULL, gr1[g], 16);
                gi1[g] = __shfl_xor_sync(FULL, gi1[g], 16);
            }
        }

        // ---- PauliZ expvals + output linear, per gate ----
        float a[4];
        #pragma unroll
        for (int g = 0; g < 4; g++) {
            float p0 = fmaf(gr0[g], gr0[g], gi0[g] * gi0[g]);
            float p1 = fmaf(gr1[g], gr1[g], gi1[g] * gi1[g]);
            float q = p0 + p1;
            float E[NHID];
            #pragma unroll
            for (int w = 0; w < 5; w++) E[w] = sgn[w] * q;
            E[5] = p0 - p1;
            #pragma unroll
            for (int off = 16; off >= 1; off >>= 1) {
                #pragma unroll
                for (int w = 0; w < NHID; w++)
                    E[w] += __shfl_xor_sync(FULL, E[w], off);
            }
            float acc = bj;
            #pragma unroll
            for (int w = 0; w < NHID; w++) acc = fmaf(wrow[w], E[w], acc);
            a[g] = acc;
        }

        // ---- LSTM update (meaningful on lanes 0..7) ----
        float fg = sigmoidf_(a[0]);
        float ig = sigmoidf_(a[1]);
        float gg = tanhfast_(a[2]);
        float og = sigmoidf_(a[3]);
        c = fmaf(fg, c, ig * gg);
        h = og * tanhfast_(c);

        if (lane < NOUT) orow[t * NOUT + lane] = h;
    }
}

extern "C" void kernel_launch(void* const* d_in, const int* in_sizes, int n_in,
                              void* d_out, int out_size) {
    (void)in_sizes; (void)n_in; (void)out_size;
    qlstm_kernel<<<NB / 4, 128>>>(
        (const float*)d_in[0],   // x
        (const float*)d_in[1],   // W_in
        (const float*)d_in[2],   // b_in
        (const float*)d_in[3],   // W_out
        (const float*)d_in[4],   // b_out
        (const float*)d_in[5],   // wf
        (const float*)d_in[6],   // wi
        (const float*)d_in[7],   // wg
        (const float*)d_in[8],   // wo
        (float*)d_out);
}

// round 3
// speedup vs baseline: 1.7188x; 1.7188x over previous
#include <cuda_runtime.h>
#include <math.h>

// B=2048, T=64, IN=8, HID=6 qubits, OUT=8, NLAYERS=2, concat=16
#define NB    2048
#define NT    64
#define NIN   8
#define NHID  6
#define NOUT  8
#define NCAT  16
#define NLAY  2

__device__ __forceinline__ float sigmoidf_(float v) {
    return 1.0f / (1.0f + __expf(-v));
}
__device__ __forceinline__ float tanhfast_(float v) {
    return 2.0f / (1.0f + __expf(-2.0f * v)) - 1.0f;
}

// Layout: one warp = 2 batch elements (one per 16-lane half).
// Within a half: octet o (8 lanes) owns gate circuits {2o, 2o+1} (f,i,g,o=0..3);
// both octets evolve the same element's state (redundant embedding, distinct gates).
// 6-qubit amp index bits: wires 0,1,2 -> lane bits 2,1,0 (within octet);
// wires 3,4,5 -> in-thread amp bits 2,1,0. 8 complex amps per thread.
__global__ __launch_bounds__(64) void qlstm_kernel(
    const float* __restrict__ x,      // [B, T, IN]
    const float* __restrict__ W_in,   // [HID, 16]
    const float* __restrict__ b_in,   // [HID]
    const float* __restrict__ W_out,  // [OUT, HID]
    const float* __restrict__ b_out,  // [OUT]
    const float* __restrict__ wf,     // [NLAY, HID]
    const float* __restrict__ wi,
    const float* __restrict__ wg,
    const float* __restrict__ wo,
    float* __restrict__ out)          // [B, T, OUT]
{
    __shared__ float2 sCS[4][NLAY][NHID];   // (cos, sin) of 0.5*weight

    const int tid = threadIdx.x;
    if (tid < 4 * NLAY * NHID) {
        const float* wp[4] = {wf, wi, wg, wo};
        int g = tid / (NLAY * NHID);
        int r = tid % (NLAY * NHID);
        float s_, c_;
        sincosf(0.5f * wp[g][r], &s_, &c_);
        sCS[g][r / NHID][r % NHID] = make_float2(c_, s_);
    }
    __syncthreads();

    const unsigned FULL = 0xffffffffu;
    const int lane   = tid & 31;
    const int warp   = blockIdx.x * (blockDim.x >> 5) + (tid >> 5);
    const int half   = lane >> 4;
    const int lane16 = lane & 15;
    const int oct    = (lane >> 3) & 1;
    const int q      = lane & 7;           // wire0,1,2 = q bits 2,1,0
    const int base   = lane & 16;
    const int b      = warp * 2 + half;

    // Hoisted weights
    float win[NCAT];
    float ybias;
    {
        int row = (lane16 < NHID) ? lane16 : 0;
        #pragma unroll
        for (int j = 0; j < NCAT; j++) win[j] = W_in[row * NCAT + j];
        ybias = b_in[row];
    }
    float wrow[NHID];
    #pragma unroll
    for (int w = 0; w < NHID; w++) wrow[w] = W_out[q * NHID + w];
    const float bj = b_out[q];

    const bool bx0 = (q >> 2) & 1;   // wire0 bit
    const bool bx1 = (q >> 1) & 1;   // wire1 bit
    const bool bx2 = q & 1;          // wire2 bit
    const bool c01 = bx0;            // CNOT(0,1) ctrl
    const bool c23 = bx2;            // CNOT(2,3) ctrl
    const int  pl  = __popc(q);      // lane popcount (for embedding phase)

    // Fused CNOT(0,1)∘CNOT(1,2) source lane: src = C01(C12(q))
    int qp = q ^ ((q >> 1) & 1);          // C12: flip bit0 if bit1
    qp ^= ((qp >> 2) & 1) << 1;           // C01: flip bit1 if bit2
    const int fsrc = (lane & 24) | qp;

    const float* xrow = x + (size_t)b * NT * NIN;
    float* orow = out + (size_t)b * NT * NOUT;

    float h = 0.0f, c = 0.0f;

    #pragma unroll 1
    for (int t = 0; t < NT; t++) {
        // ---- y = [h, x_t] @ W_in^T + b_in (per half-warp) ----
        float v = (lane16 < 8) ? h : xrow[t * NIN + q];
        float y = ybias;
        #pragma unroll
        for (int j = 0; j < NCAT; j++) {
            float vj = __shfl_sync(FULL, v, base | j);
            y = fmaf(win[j], vj, y);
        }
        float myS, myC;
        __sincosf(0.5f * y, &myS, &myC);
        float cw[NHID], sw[NHID];
        #pragma unroll
        for (int w = 0; w < NHID; w++) {
            cw[w] = __shfl_sync(FULL, myC, base | w);
            sw[w] = __shfl_sync(FULL, myS, base | w);
        }

        // ---- embedding state in closed form (product state) ----
        // amp = (-i)^popc(x) * prod_w (x_w ? s_w : c_w)
        float er[8], ei[8];
        {
            float lp = (bx0 ? sw[0] : cw[0]) * (bx1 ? sw[1] : cw[1])
                     * (bx2 ? sw[2] : cw[2]);
            float ap[8];
            float c34 = cw[3] * cw[4], c3s4 = cw[3] * sw[4];
            float s34 = sw[3] * cw[4], s3s4 = sw[3] * sw[4];
            ap[0] = c34  * cw[5]; ap[1] = c34  * sw[5];
            ap[2] = c3s4 * cw[5]; ap[3] = c3s4 * sw[5];
            ap[4] = s34  * cw[5]; ap[5] = s34  * sw[5];
            ap[6] = s3s4 * cw[5]; ap[7] = s3s4 * sw[5];
            #pragma unroll
            for (int a = 0; a < 8; a++) {
                float m = lp * ap[a];
                int k = (pl + __popc(a)) & 3;   // (-i)^k
                er[a] = (k == 0) ? m : ((k == 2) ? -m : 0.0f);
                ei[a] = (k == 1) ? -m : ((k == 3) ? m : 0.0f);
            }
        }

        // ---- two gate circuits per thread ----
        float gr[2][8], gi[2][8];
        #pragma unroll
        for (int s = 0; s < 2; s++)
            #pragma unroll
            for (int a = 0; a < 8; a++) { gr[s][a] = er[a]; gi[s][a] = ei[a]; }

        #pragma unroll
        for (int l = 0; l < NLAY; l++) {
            // RX, lane wires 0..2 (shfl masks 4,2,1)
            #pragma unroll
            for (int w = 0; w < 3; w++) {
                const int m = 4 >> w;
                #pragma unroll
                for (int s = 0; s < 2; s++) {
                    float2 cs = sCS[2 * oct + s][l][w];
                    #pragma unroll
                    for (int a = 0; a < 8; a++) {
                        float pr = __shfl_xor_sync(FULL, gr[s][a], m);
                        float pi = __shfl_xor_sync(FULL, gi[s][a], m);
                        gr[s][a] = fmaf(cs.x, gr[s][a], cs.y * pi);
                        gi[s][a] = fmaf(cs.x, gi[s][a], -cs.y * pr);
                    }
                }
            }
            // RX, in-thread wires 3..5 (amp masks 4,2,1)
            #pragma unroll
            for (int w = 3; w < 6; w++) {
                const int m = 4 >> (w - 3);
                #pragma unroll
                for (int s = 0; s < 2; s++) {
                    float2 cs = sCS[2 * oct + s][l][w];
                    float nr[8], ni[8];
                    #pragma unroll
                    for (int a = 0; a < 8; a++) {
                        nr[a] = fmaf(cs.x, gr[s][a], cs.y * gi[s][a ^ m]);
                        ni[a] = fmaf(cs.x, gi[s][a], -cs.y * gr[s][a ^ m]);
                    }
                    #pragma unroll
                    for (int a = 0; a < 8; a++) { gr[s][a] = nr[a]; gi[s][a] = ni[a]; }
                }
            }
            if (l != NLAY - 1) {
                // Fused CNOT(0,1)+CNOT(1,2): one lane permutation
                #pragma unroll
                for (int s = 0; s < 2; s++)
                    #pragma unroll
                    for (int a = 0; a < 8; a++) {
                        gr[s][a] = __shfl_sync(FULL, gr[s][a], fsrc);
                        gi[s][a] = __shfl_sync(FULL, gi[s][a], fsrc);
                    }
                // CNOT(2,3): ctrl lane bit0, tgt amp bit2 (cond swap)
                #pragma unroll
                for (int s = 0; s < 2; s++)
                    #pragma unroll
                    for (int a = 0; a < 4; a++) {
                        float tr = gr[s][a], ti = gi[s][a];
                        gr[s][a]     = c23 ? gr[s][a + 4] : gr[s][a];
                        gi[s][a]     = c23 ? gi[s][a + 4] : gi[s][a];
                        gr[s][a + 4] = c23 ? tr : gr[s][a + 4];
                        gi[s][a + 4] = c23 ? ti : gi[s][a + 4];
                    }
                // CNOT(3,4): swap (4,6),(5,7); CNOT(4,5): swap (2,3),(6,7)
                #pragma unroll
                for (int s = 0; s < 2; s++) {
                    float tr;
                    tr = gr[s][4]; gr[s][4] = gr[s][6]; gr[s][6] = tr;
                    tr = gi[s][4]; gi[s][4] = gi[s][6]; gi[s][6] = tr;
                    tr = gr[s][5]; gr[s][5] = gr[s][7]; gr[s][7] = tr;
                    tr = gi[s][5]; gi[s][5] = gi[s][7]; gi[s][7] = tr;
                    tr = gr[s][2]; gr[s][2] = gr[s][3]; gr[s][3] = tr;
                    tr = gi[s][2]; gi[s][2] = gi[s][3]; gi[s][3] = tr;
                    tr = gr[s][6]; gr[s][6] = gr[s][7]; gr[s][7] = tr;
                    tr = gi[s][6]; gi[s][6] = gi[s][7]; gi[s][7] = tr;
                }
                // CNOT(5,0): odd amps exchange across lane mask 4
                #pragma unroll
                for (int s = 0; s < 2; s++)
                    #pragma unroll
                    for (int a = 1; a < 8; a += 2) {
                        gr[s][a] = __shfl_xor_sync(FULL, gr[s][a], 4);
                        gi[s][a] = __shfl_xor_sync(FULL, gi[s][a], 4);
                    }
            }
            // Last layer: CNOT ring elided; permutation folded into expval signs.
        }

        // ---- expvals with permutation-folded signs + output linear ----
        // sign bits (pre-permutation index x): E0:{x1,x2}&{x3^x4^x5}... derived:
        //   E0 = lane(x1^x2) * A5;  E1 = lane(x0^x1) * A
        //   E2 = lane(x0^x1^x2)*A;  E3 = lane(x0x1x2)*A3
        //   E4 = lane(x0x1x2)*A4;   E5 = lane(x0x1x2)*A5
        // A  = sum p; A3 = sign(x3); A4 = sign(x3^x4); A5 = sign(x3^x4^x5)
        float acc[2];
        #pragma unroll
        for (int s = 0; s < 2; s++) {
            float p[8];
            #pragma unroll
            for (int a = 0; a < 8; a++)
                p[a] = fmaf(gr[s][a], gr[s][a], gi[s][a] * gi[s][a]);
            float t01 = p[0] + p[1], t23 = p[2] + p[3];
            float t45 = p[4] + p[5], t67 = p[6] + p[7];
            float slo = t01 + t23, shi = t45 + t67;
            float A  = slo + shi;
            float A3 = slo - shi;
            float A4 = (t01 + t67) - (t23 + t45);
            float A5 = ((p[0] + p[3]) + (p[5] + p[6]))
                     - ((p[1] + p[2]) + (p[4] + p[7]));

            float E0, E1, E2, E3, E4, E5, u, tt;
            // A -> E1 {x0,x1}, E2 {x0,x1,x2}
            u = A;
            tt = __shfl_xor_sync(FULL, u, 4); u = bx0 ? tt - u : u - tt;
            tt = __shfl_xor_sync(FULL, u, 2); u = bx1 ? tt - u : u - tt;
            tt = __shfl_xor_sync(FULL, u, 1);
            E1 = u + tt; E2 = bx2 ? tt - u : u - tt;
            // A3 -> E3 {x0,x1,x2}
            u = A3;
            tt = __shfl_xor_sync(FULL, u, 4); u = bx0 ? tt - u : u - tt;
            tt = __shfl_xor_sync(FULL, u, 2); u = bx1 ? tt - u : u - tt;
            tt = __shfl_xor_sync(FULL, u, 1); E3 = bx2 ? tt - u : u - tt;
            // A4 -> E4 {x0,x1,x2}
            u = A4;
            tt = __shfl_xor_sync(FULL, u, 4); u = bx0 ? tt - u : u - tt;
            tt = __shfl_xor_sync(FULL, u, 2); u = bx1 ? tt - u : u - tt;
            tt = __shfl_xor_sync(FULL, u, 1); E4 = bx2 ? tt - u : u - tt;
            // A5 -> E0 {x1,x2}, E5 {x0,x1,x2}
            u = A5;
            tt = __shfl_xor_sync(FULL, u, 2); u = bx1 ? tt - u : u - tt;
            tt = __shfl_xor_sync(FULL, u, 1); u = bx2 ? tt - u : u - tt;
            tt = __shfl_xor_sync(FULL, u, 4);
            E0 = u + tt; E5 = bx0 ? tt - u : u - tt;

            float a2 = bj;
            a2 = fmaf(wrow[0], E0, a2);
            a2 = fmaf(wrow[1], E1, a2);
            a2 = fmaf(wrow[2], E2, a2);
            a2 = fmaf(wrow[3], E3, a2);
            a2 = fmaf(wrow[4], E4, a2);
            a2 = fmaf(wrow[5], E5, a2);
            acc[s] = a2;
        }

        // ---- gather 4 gates for dim q ----
        float af = __shfl_sync(FULL, acc[0], base | q);
        float ai = __shfl_sync(FULL, acc[1], base | q);
        float ag = __shfl_sync(FULL, acc[0], base | 8 | q);
        float ao = __shfl_sync(FULL, acc[1], base | 8 | q);

        float fg = sigmoidf_(af);
        float ig = sigmoidf_(ai);
        float gg = tanhfast_(ag);
        float og = sigmoidf_(ao);
        c = fmaf(fg, c, ig * gg);
        h = og * tanhfast_(c);

        if (lane16 < NOUT) orow[t * NOUT + q] = h;
    }
    (void)c01;
}

extern "C" void kernel_launch(void* const* d_in, const int* in_sizes, int n_in,
                              void* d_out, int out_size) {
    (void)in_sizes; (void)n_in; (void)out_size;
    // 2 warps/block, 2 elements/warp -> 4 elements/block, 512 blocks
    qlstm_kernel<<<NB / 4, 64>>>(
        (const float*)d_in[0],   // x
        (const float*)d_in[1],   // W_in
        (const float*)d_in[2],   // b_in
        (const float*)d_in[3],   // W_out
        (const float*)d_in[4],   // b_out
        (const float*)d_in[5],   // wf
        (const float*)d_in[6],   // wi
        (const float*)d_in[7],   // wg
        (const float*)d_in[8],   // wo
        (float*)d_out);
}